// round 2
// baseline (speedup 1.0000x reference)
#include <cuda_runtime.h>
#include <cstdint>

typedef unsigned long long U64;

// ---- problem constants ----
#define NB 4
#define NZC 64
#define NE_ 16
#define NNE 16384
#define NFR 32
#define NHW 1024
#define NP 4096

// output offsets (float elements)
#define OFF_ZL   67108864
#define OFF_TI   67174400
#define OFF_ZHQ  67178496
#define OFF_DEC  67244032

// ---- static scratch ----
__device__ float g_z[NP * NE_];           // quant-conv output [p][16]
__device__ float g_h[64 * NP];            // pcn body, k-major [oc][p]
__device__ float g_w2t[64 * NNE];         // W2 transposed [k][n]
__device__ float g_cn[NNE];               // |codebook|^2
__device__ float g_zlq[NB * 64 * NHW];    // post-quant conv out
__device__ float g_t1[NB * 64 * NHW];     // dec1 relu (32x32)
__device__ float g_t2[NB * 64 * 4096];    // fused relu (64x64)
__device__ U64 g_amax[NP];                // logits argmax packed
__device__ U64 g_avq[NP];                 // VQ argmin packed

// ---- helpers ----
__device__ __forceinline__ unsigned ordf(float f) {
    unsigned u = __float_as_uint(f);
    return (u & 0x80000000u) ? ~u : (u | 0x80000000u);
}
__device__ __forceinline__ U64 pk2(float lo, float hi) {
    U64 r; asm("mov.b64 %0,{%1,%2};" : "=l"(r) : "f"(lo), "f"(hi)); return r;
}
__device__ __forceinline__ U64 fma2(U64 a, U64 b, U64 c) {
    U64 d; asm("fma.rn.f32x2 %0,%1,%2,%3;" : "=l"(d) : "l"(a), "l"(b), "l"(c)); return d;
}
__device__ __forceinline__ void unp2(U64 v, float& a, float& b) {
    asm("mov.b64 {%0,%1},%2;" : "=f"(a), "=f"(b) : "l"(v));
}
__device__ __forceinline__ U64 wred(U64 v) {
#pragma unroll
    for (int o = 16; o; o >>= 1) {
        U64 t = __shfl_down_sync(0xffffffffu, v, o);
        if (t > v) v = t;
    }
    return v;
}
__device__ __forceinline__ float decode_w(const void* p) {
    int iv = *(const int*)p;
    if (iv > -100000000 && iv < 100000000) return (float)iv;  // int payload (int32/int64 LE)
    return __int_as_float(iv);                                // float bits
}

// ---------------- K0: init packed-argmax scratch ----------------
__global__ void k0_init() {
    int i = blockIdx.x * 256 + threadIdx.x;
    if (i < NP) { g_amax[i] = 0ull; g_avq[i] = 0ull; }
}

// ---------------- K1: two 1x1 convs ----------------
__global__ void k1_quant(const float* __restrict__ z_t, const float* __restrict__ qw,
                         const float* __restrict__ qb, const float* __restrict__ zlpre,
                         const float* __restrict__ lw, const float* __restrict__ lb,
                         float* __restrict__ out) {
    int id = blockIdx.x * 256 + threadIdx.x;     // 131072
    int which = id >> 16;
    int sub = id & 65535;
    int b = sub >> 14, e = (sub >> 10) & 15, hw = sub & 1023;
    if (which == 0) {
        const float* src = z_t + b * 65536 + hw;
        const float* w = qw + e * 64;
        float acc = qb[e];
#pragma unroll 16
        for (int c = 0; c < 64; c++) acc = fmaf(w[c], src[c * 1024], acc);
        g_z[(b * 1024 + hw) * 16 + e] = acc;
    } else {
        const float* src = zlpre + b * 65536 + hw;
        const float* w = lw + e * 64;
        float acc = lb[e];
#pragma unroll 16
        for (int c = 0; c < 64; c++) acc = fmaf(w[c], src[c * 1024], acc);
        out[OFF_ZL + b * 16384 + e * 1024 + hw] = acc;
    }
}

// ---------------- Kcn: |codebook|^2 ----------------
__global__ void kcn(const float* __restrict__ cb) {
    int n = blockIdx.x * 256 + threadIdx.x;  // 16384
    float s = 0.f;
#pragma unroll
    for (int q = 0; q < 4; q++) {
        float4 v = *(const float4*)&cb[(size_t)n * 16 + q * 4];
        s = fmaf(v.x, v.x, s); s = fmaf(v.y, v.y, s);
        s = fmaf(v.z, v.z, s); s = fmaf(v.w, v.w, s);
    }
    g_cn[n] = s;
}

// ---------------- Kt: transpose W2 [n][k] -> [k][n] ----------------
__global__ void kt_w2t(const float* __restrict__ w2) {
    __shared__ float t[64 * 65];
    int tid = threadIdx.x;
    int n0 = blockIdx.x * 64;
#pragma unroll
    for (int r = 0; r < 4; r++) {
        int f = tid + 256 * r;                 // f < 1024
        int nl = f >> 4, kq = f & 15;
        float4 v = *(const float4*)&w2[(size_t)(n0 + nl) * 64 + kq * 4];
        t[nl * 65 + kq * 4 + 0] = v.x; t[nl * 65 + kq * 4 + 1] = v.y;
        t[nl * 65 + kq * 4 + 2] = v.z; t[nl * 65 + kq * 4 + 3] = v.w;
    }
    __syncthreads();
#pragma unroll
    for (int r = 0; r < 4; r++) {
        int f = tid + 256 * r;
        int k = f >> 4, nq = f & 15;
        float4 v;
        v.x = t[(nq * 4 + 0) * 65 + k];
        v.y = t[(nq * 4 + 1) * 65 + k];
        v.z = t[(nq * 4 + 2) * 65 + k];
        v.w = t[(nq * 4 + 3) * 65 + k];
        *(float4*)&g_w2t[(size_t)k * NNE + n0 + nq * 4] = v;
    }
}

// ---------------- K2: VQ argmin (argmax of z.c - 0.5|c|^2), f32x2 packed ----------------
__global__ void __launch_bounds__(256) k2_vq(const float* __restrict__ cb) {
    __shared__ float cs[128 * 17];
    int tid = threadIdx.x;
    int wr = tid >> 5, lane = tid & 31;
    int pb = blockIdx.x * 32 + wr * 4;          // 4 consecutive p per thread (pairs)
    int cbase = blockIdx.y * 4096;

    U64 z2[2][16];
#pragma unroll
    for (int i2 = 0; i2 < 2; i2++) {
        float za[16], zb[16];
#pragma unroll
        for (int q = 0; q < 4; q++) {
            float4 v0 = *(const float4*)&g_z[(pb + 2 * i2) * 16 + q * 4];
            float4 v1 = *(const float4*)&g_z[(pb + 2 * i2 + 1) * 16 + q * 4];
            za[q * 4 + 0] = v0.x; za[q * 4 + 1] = v0.y; za[q * 4 + 2] = v0.z; za[q * 4 + 3] = v0.w;
            zb[q * 4 + 0] = v1.x; zb[q * 4 + 1] = v1.y; zb[q * 4 + 2] = v1.z; zb[q * 4 + 3] = v1.w;
        }
#pragma unroll
        for (int k = 0; k < 16; k++) z2[i2][k] = pk2(za[k], zb[k]);
    }

    float best[4]; int bn[4];
#pragma unroll
    for (int i = 0; i < 4; i++) { best[i] = -3.4e38f; bn[i] = 0; }

    for (int ch = 0; ch < 32; ch++) {
        int c0 = cbase + ch * 128;
        __syncthreads();
#pragma unroll
        for (int r = 0; r < 2; r++) {
            int f = tid + 256 * r;              // f < 512
            int code = f >> 2, kq = f & 3;
            float4 v = *(const float4*)&cb[(size_t)(c0 + code) * 16 + kq * 4];
            cs[code * 17 + kq * 4 + 0] = v.x; cs[code * 17 + kq * 4 + 1] = v.y;
            cs[code * 17 + kq * 4 + 2] = v.z; cs[code * 17 + kq * 4 + 3] = v.w;
        }
        __syncthreads();

        U64 acc2[2][4];
#pragma unroll
        for (int i2 = 0; i2 < 2; i2++)
#pragma unroll
            for (int j = 0; j < 4; j++) acc2[i2][j] = 0ull;

#pragma unroll
        for (int k = 0; k < 16; k++) {
            U64 cvp[4];
#pragma unroll
            for (int j = 0; j < 4; j++) {
                float cv = cs[(lane + 32 * j) * 17 + k];
                cvp[j] = pk2(cv, cv);
            }
#pragma unroll
            for (int i2 = 0; i2 < 2; i2++)
#pragma unroll
                for (int j = 0; j < 4; j++) acc2[i2][j] = fma2(z2[i2][k], cvp[j], acc2[i2][j]);
        }

#pragma unroll
        for (int j = 0; j < 4; j++) {
            int n = c0 + lane + 32 * j;
            float hn = 0.5f * __ldg(&g_cn[n]);
#pragma unroll
            for (int i2 = 0; i2 < 2; i2++) {
                float s0, s1; unp2(acc2[i2][j], s0, s1);
                s0 -= hn; s1 -= hn;
                int i = 2 * i2;
                if (s0 > best[i]) { best[i] = s0; bn[i] = n; }
                if (s1 > best[i + 1]) { best[i + 1] = s1; bn[i + 1] = n; }
            }
        }
    }
#pragma unroll
    for (int i = 0; i < 4; i++) {
        U64 pk = ((U64)ordf(best[i]) << 32) | (unsigned)(NNE - 1 - bn[i]);
        pk = wred(pk);
        if (lane == 0) atomicMax(&g_avq[pb + i], pk);
    }
}

// ---------------- K2b: finalize VQ -> target_index + z_hq ----------------
__global__ void k2b_fin(const float* __restrict__ cb, float* __restrict__ out) {
    int id = blockIdx.x * 256 + threadIdx.x;  // 65536
    int p = id >> 4, e = id & 15;
    U64 pk = g_avq[p];
    int idx = NNE - 1 - (int)(unsigned)(pk & 0xffffffffu);
    int b = p >> 10, hw = p & 1023;
    out[OFF_ZHQ + b * 16384 + e * 1024 + hw] = __ldg(&cb[(size_t)idx * 16 + e]);
    if (e == 0) out[OFF_TI + p] = (float)idx;
}

// ---------------- K3: pcn 7x7 conv + relu -> g_h (k-major) ----------------
__global__ void __launch_bounds__(128) k3_pcn(const float* __restrict__ zl,
                                              const float* __restrict__ w1,
                                              const float* __restrict__ b1) {
    __shared__ float si[16 * 7 * 38];
    __shared__ float sw[8 * 784];
    int tid = threadIdx.x;
    int ocg = blockIdx.x, y = blockIdx.y, b = blockIdx.z;
    for (int idx = tid; idx < 16 * 266; idx += 128) {
        int ic = idx / 266; int rem = idx - ic * 266;
        int ky = rem / 38; int xx = rem - ky * 38;
        int yy = y - 3 + ky, xr = xx - 3;
        float v = 0.f;
        if ((unsigned)yy < 32u && (unsigned)xr < 32u)
            v = zl[b * 16384 + ic * 1024 + yy * 32 + xr];
        si[idx] = v;
    }
    for (int idx = tid; idx < 8 * 784; idx += 128) {
        int ol = idx / 784; int rem = idx - ol * 784;
        sw[idx] = w1[(ocg * 8 + ol) * 784 + rem];
    }
    __syncthreads();
    int ol = tid >> 4, xg = tid & 15, x0 = xg * 2;
    int oc = ocg * 8 + ol;
    float a0 = b1[oc], a1 = a0;
    for (int ic = 0; ic < 16; ic++) {
#pragma unroll
        for (int ky = 0; ky < 7; ky++) {
            const float* sp = &si[ic * 266 + ky * 38 + x0];
            float r[8];
#pragma unroll
            for (int j = 0; j < 8; j++) r[j] = sp[j];
            const float* wp = &sw[ol * 784 + ic * 49 + ky * 7];
#pragma unroll
            for (int kx = 0; kx < 7; kx++) {
                float wv = wp[kx];
                a0 = fmaf(r[kx], wv, a0);
                a1 = fmaf(r[kx + 1], wv, a1);
            }
        }
    }
    a0 = fmaxf(a0, 0.f); a1 = fmaxf(a1, 0.f);
    int p = b * 1024 + y * 32 + x0;
    g_h[oc * 4096 + p] = a0;
    g_h[oc * 4096 + p + 1] = a1;
}

// ---------------- K4: logits GEMM (f32x2) + bias + store + fused argmax ----------------
__global__ void __launch_bounds__(256) k4_logits(const float* __restrict__ b2,
                                                 float* __restrict__ out) {
    __shared__ __align__(16) float hsT[32 * 64];
    __shared__ __align__(16) float wsT[32 * 128];
    int tid = threadIdx.x;
    int n0 = blockIdx.x * 128, p0 = blockIdx.y * 64;
    int ty = tid >> 5, tx = tid & 31;

    U64 acc2[4][4];
#pragma unroll
    for (int i = 0; i < 4; i++)
#pragma unroll
        for (int j = 0; j < 4; j++) acc2[i][j] = 0ull;

    for (int kc = 0; kc < 2; kc++) {
        __syncthreads();
#pragma unroll
        for (int r = 0; r < 2; r++) {
            int f = tid + 256 * r;  // 512 float4
            int k = f >> 4, pq = f & 15;
            *(float4*)&hsT[k * 64 + pq * 4] =
                *(const float4*)&g_h[(kc * 32 + k) * 4096 + p0 + pq * 4];
        }
#pragma unroll
        for (int r = 0; r < 4; r++) {
            int f = tid + 256 * r;  // 1024 float4
            int k = f >> 5, nq = f & 31;
            *(float4*)&wsT[k * 128 + nq * 4] =
                *(const float4*)&g_w2t[(size_t)(kc * 32 + k) * NNE + n0 + nq * 4];
        }
        __syncthreads();
#pragma unroll
        for (int k = 0; k < 32; k++) {
            ulonglong2 aa0 = *(ulonglong2*)&hsT[k * 64 + ty * 8];
            ulonglong2 aa1 = *(ulonglong2*)&hsT[k * 64 + ty * 8 + 4];
            U64 a2[4] = {aa0.x, aa0.y, aa1.x, aa1.y};
            float4 bv = *(float4*)&wsT[k * 128 + tx * 4];
            U64 bb[4] = {pk2(bv.x, bv.x), pk2(bv.y, bv.y), pk2(bv.z, bv.z), pk2(bv.w, bv.w)};
#pragma unroll
            for (int i = 0; i < 4; i++)
#pragma unroll
                for (int j = 0; j < 4; j++) acc2[i][j] = fma2(a2[i], bb[j], acc2[i][j]);
        }
    }

    float4 bias = *(const float4*)&b2[n0 + tx * 4];
    float bj[4] = {bias.x, bias.y, bias.z, bias.w};
#pragma unroll
    for (int i = 0; i < 4; i++) {
        float s0[4], s1[4];
#pragma unroll
        for (int j = 0; j < 4; j++) {
            unp2(acc2[i][j], s0[j], s1[j]);
            s0[j] += bj[j]; s1[j] += bj[j];
        }
        int pr = p0 + ty * 8 + 2 * i;
        *(float4*)&out[(size_t)pr * NNE + n0 + tx * 4] = make_float4(s0[0], s0[1], s0[2], s0[3]);
        *(float4*)&out[(size_t)(pr + 1) * NNE + n0 + tx * 4] = make_float4(s1[0], s1[1], s1[2], s1[3]);
        // fused argmax per row (lowest index on ties)
        float mb0 = s0[0]; int mn0 = n0 + tx * 4;
        float mb1 = s1[0]; int mn1 = n0 + tx * 4;
#pragma unroll
        for (int j = 1; j < 4; j++) {
            if (s0[j] > mb0) { mb0 = s0[j]; mn0 = n0 + tx * 4 + j; }
            if (s1[j] > mb1) { mb1 = s1[j]; mn1 = n0 + tx * 4 + j; }
        }
        U64 pk0 = ((U64)ordf(mb0) << 32) | (unsigned)(NNE - 1 - mn0);
        U64 pk1 = ((U64)ordf(mb1) << 32) | (unsigned)(NNE - 1 - mn1);
        pk0 = wred(pk0); pk1 = wred(pk1);
        if (tx == 0) {
            atomicMax(&g_amax[pr], pk0);
            atomicMax(&g_amax[pr + 1], pk1);
        }
    }
}

// ---------------- K5: z_lq = post_quant_conv(codebook[top_index]) ----------------
__global__ void k5_zlq(const float* __restrict__ cb, const float* __restrict__ pqw,
                       const float* __restrict__ pqb) {
    int id = blockIdx.x * 256 + threadIdx.x;  // 262144
    int p = id >> 6, zc = id & 63;
    U64 pk = g_amax[p];
    int idx = NNE - 1 - (int)(unsigned)(pk & 0xffffffffu);
    const float* c = &cb[(size_t)idx * 16];
    float a = pqb[zc];
#pragma unroll
    for (int k = 0; k < 16; k++) a = fmaf(pqw[zc * 16 + k], __ldg(&c[k]), a);
    g_zlq[((p >> 10) * 64 + zc) * 1024 + (p & 1023)] = a;
}

// ---------------- conv3x3 (dec1 / fuse) ----------------
// MODE 0: g_t1 = relu(conv(g_zlq)) at 32x32
// MODE 1: g_t2 = relu(up2(g_t1) + w*conv(fuse_feat)) at 64x64
template <int W, int MODE>
__global__ void __launch_bounds__(256) conv3(const float* __restrict__ in,
                                             const float* __restrict__ wt,
                                             const float* __restrict__ bs,
                                             const void* __restrict__ wraw) {
    constexpr int WP = W + 2;
    constexpr int OCT = W / 8;  // oc per thread
    __shared__ float sin_[16][6][WP];
    __shared__ float sw[32 * 144];
    int tid = threadIdx.x;
    int strip = blockIdx.x, ocg = blockIdx.y, b = blockIdx.z;
    int x = tid % W, og = tid / W;
    const float* src = (MODE == 0) ? (const float*)g_zlq : in;
    float acc[OCT][4];
#pragma unroll
    for (int t = 0; t < OCT; t++)
#pragma unroll
        for (int y = 0; y < 4; y++) acc[t][y] = 0.f;
    int y0 = strip * 4;

    for (int icc = 0; icc < 4; icc++) {
        __syncthreads();
        for (int idx = tid; idx < 16 * 6 * WP; idx += 256) {
            int ic = idx / (6 * WP); int rem = idx - ic * 6 * WP;
            int r = rem / WP; int c = rem - r * WP;
            int gy = y0 - 1 + r, gx = c - 1;
            float v = 0.f;
            if ((unsigned)gy < (unsigned)W && (unsigned)gx < (unsigned)W)
                v = src[((b * 64 + icc * 16 + ic) * W + gy) * W + gx];
            sin_[ic][r][c] = v;
        }
        for (int idx = tid; idx < 32 * 144; idx += 256) {
            int ol = idx / 144; int rem = idx - ol * 144;
            sw[idx] = wt[(ocg * 32 + ol) * 576 + icc * 144 + rem];
        }
        __syncthreads();
        for (int ic = 0; ic < 16; ic++) {
            float rv[6][3];
#pragma unroll
            for (int r = 0; r < 6; r++)
#pragma unroll
                for (int cc = 0; cc < 3; cc++) rv[r][cc] = sin_[ic][r][x + cc];
#pragma unroll
            for (int t = 0; t < OCT; t++) {
                const float* wp = &sw[(og * OCT + t) * 144 + ic * 9];
#pragma unroll
                for (int ky = 0; ky < 3; ky++)
#pragma unroll
                    for (int kx = 0; kx < 3; kx++) {
                        float wv = wp[ky * 3 + kx];
#pragma unroll
                        for (int y = 0; y < 4; y++)
                            acc[t][y] = fmaf(rv[y + ky][kx], wv, acc[t][y]);
                    }
            }
        }
    }
    float ws = 1.f;
    if (MODE == 1) ws = decode_w(wraw);
#pragma unroll
    for (int t = 0; t < OCT; t++) {
        int oc = ocg * 32 + og * OCT + t;
        float bv = bs[oc];
#pragma unroll
        for (int y = 0; y < 4; y++) {
            int oy = y0 + y;
            float v = acc[t][y] + bv;
            if (MODE == 0) {
                v = fmaxf(v, 0.f);
                g_t1[((b * 64 + oc) << 10) + oy * 32 + x] = v;
            } else {
                float base = g_t1[((b * 64 + oc) << 10) + ((oy >> 1) << 5) + (x >> 1)];
                v = fmaxf(base + ws * v, 0.f);
                g_t2[((b * 64 + oc) << 12) + (oy << 6) + x] = v;
            }
        }
    }
}

// ---------------- K8: dec2 = conv3x3(up2(g_t2)) -> out, fused upsample ----------------
__global__ void __launch_bounds__(256) k8_dec2(const float* __restrict__ w2,
                                               const float* __restrict__ b2,
                                               float* __restrict__ out) {
    __shared__ float wq[16][64];  // [(py*2+px)*4 + j*2+i][c]
    int tid = threadIdx.x;
    for (int idx = tid; idx < 1024; idx += 256) {
        int c = idx & 63; int m = idx >> 6;
        int py = m >> 3, px = (m >> 2) & 1, j = (m >> 1) & 1, i = m & 1;
        int ky0 = (py == 0) ? (j == 0 ? 0 : 1) : (j == 0 ? 0 : 2);
        int kyn = (py == 0) ? (j == 0 ? 1 : 2) : (j == 0 ? 2 : 1);
        int kx0 = (px == 0) ? (i == 0 ? 0 : 1) : (i == 0 ? 0 : 2);
        int kxn = (px == 0) ? (i == 0 ? 1 : 2) : (i == 0 ? 2 : 1);
        float s = 0.f;
        for (int ky = ky0; ky < ky0 + kyn; ky++)
            for (int kx = kx0; kx < kx0 + kxn; kx++)
                s += w2[c * 9 + ky * 3 + kx];
        wq[m][c] = s;
    }
    __syncthreads();
    int q = blockIdx.x * 256 + tid;  // 16384 quads
    int b = q >> 12; int r = q & 4095; int qy = r >> 6; int qx = r & 63;
    float bb = b2[0];
    float acc[2][2] = {{bb, bb}, {bb, bb}};
    for (int c = 0; c < 64; c++) {
        const float* base = &g_t2[((b * 64 + c) << 12)];
        float v[3][3];
#pragma unroll
        for (int dj = 0; dj < 3; dj++) {
            int ry = qy - 1 + dj;
#pragma unroll
            for (int di = 0; di < 3; di++) {
                int rx = qx - 1 + di;
                v[dj][di] = ((unsigned)ry < 64u && (unsigned)rx < 64u)
                                ? __ldg(&base[(ry << 6) + rx]) : 0.f;
            }
        }
#pragma unroll
        for (int py = 0; py < 2; py++)
#pragma unroll
            for (int px = 0; px < 2; px++)
#pragma unroll
                for (int j = 0; j < 2; j++)
#pragma unroll
                    for (int i = 0; i < 2; i++)
                        acc[py][px] = fmaf(wq[(py * 2 + px) * 4 + j * 2 + i][c],
                                           v[py + j][px + i], acc[py][px]);
    }
#pragma unroll
    for (int py = 0; py < 2; py++)
#pragma unroll
        for (int px = 0; px < 2; px++)
            out[OFF_DEC + (b << 14) + ((2 * qy + py) << 7) + 2 * qx + px] = acc[py][px];
}

// ---------------- launch ----------------
extern "C" void kernel_launch(void* const* d_in, const int* in_sizes, int n_in,
                              void* d_out, int out_size) {
    const float* z_t      = (const float*)d_in[0];
    const float* z_l_pre  = (const float*)d_in[1];
    const float* fuse_feat= (const float*)d_in[2];
    const void*  wraw     = d_in[3];
    const float* quant_w  = (const float*)d_in[4];
    const float* quant_b  = (const float*)d_in[5];
    const float* codebook = (const float*)d_in[6];
    const float* lrq_w    = (const float*)d_in[7];
    const float* lrq_b    = (const float*)d_in[8];
    const float* pcn_w1   = (const float*)d_in[9];
    const float* pcn_b1   = (const float*)d_in[10];
    const float* pcn_w2   = (const float*)d_in[11];
    const float* pcn_b2   = (const float*)d_in[12];
    const float* pq_w     = (const float*)d_in[13];
    const float* pq_b     = (const float*)d_in[14];
    const float* dec_w1   = (const float*)d_in[15];
    const float* dec_b1   = (const float*)d_in[16];
    const float* fuse_w   = (const float*)d_in[17];
    const float* fuse_b   = (const float*)d_in[18];
    const float* dec_w2   = (const float*)d_in[19];
    const float* dec_b2   = (const float*)d_in[20];
    float* out = (float*)d_out;

    k0_init<<<16, 256>>>();
    k1_quant<<<512, 256>>>(z_t, quant_w, quant_b, z_l_pre, lrq_w, lrq_b, out);
    kcn<<<64, 256>>>(codebook);
    kt_w2t<<<256, 256>>>(pcn_w2);
    k2_vq<<<dim3(128, 4), 256>>>(codebook);
    k2b_fin<<<256, 256>>>(codebook, out);
    k3_pcn<<<dim3(8, 32, 4), 128>>>(out + OFF_ZL, pcn_w1, pcn_b1);
    k4_logits<<<dim3(128, 64), 256>>>(pcn_b2, out);
    k5_zlq<<<1024, 256>>>(codebook, pq_w, pq_b);
    conv3<32, 0><<<dim3(8, 2, 4), 256>>>(nullptr, dec_w1, dec_b1, nullptr);
    conv3<64, 1><<<dim3(16, 2, 4), 256>>>(fuse_feat, fuse_w, fuse_b, wraw);
    k8_dec2<<<64, 256>>>(dec_w2, dec_b2, out);
}

// round 10
// speedup vs baseline: 1.1084x; 1.1084x over previous
#include <cuda_runtime.h>
#include <cuda_bf16.h>
#include <cstdint>

typedef unsigned long long U64;

// ---- problem constants ----
#define NB 4
#define NZC 64
#define NE_ 16
#define NNE 16384
#define NFR 32
#define NHW 1024
#define NP 4096

// output offsets (float elements)
#define OFF_ZL   67108864
#define OFF_TI   67174400
#define OFF_ZHQ  67178496
#define OFF_DEC  67244032

// ---- static scratch ----
__device__ float g_z[NP * NE_];             // quant-conv output [p][16]
__device__ float g_h[64 * NP];              // pcn body, k-major [oc][p]
__device__ float g_cn[NNE];                 // |codebook|^2
__device__ float g_zlq[NB * 64 * NHW];      // post-quant conv out
__device__ float g_t1[NB * 64 * NHW];       // dec1 relu (32x32)
__device__ float g_t2[NB * 64 * 4096];      // fused relu (64x64)
__device__ U64 g_amax[NP];                  // logits argmax packed
__device__ U64 g_avq[NP];                   // VQ argmin packed
__device__ uint32_t g_bext[(size_t)NNE * 96];  // B_ext [n][96 u32] bf16x2 (6.3MB)
__device__ uint32_t g_aext[NP * 96];        // A_ext [p][96 u32] bf16x2 (1.5MB)

// ---- generic helpers ----
__device__ __forceinline__ unsigned ordf(float f) {
    unsigned u = __float_as_uint(f);
    return (u & 0x80000000u) ? ~u : (u | 0x80000000u);
}
__device__ __forceinline__ U64 pk2(float lo, float hi) {
    U64 r; asm("mov.b64 %0,{%1,%2};" : "=l"(r) : "f"(lo), "f"(hi)); return r;
}
__device__ __forceinline__ U64 fma2(U64 a, U64 b, U64 c) {
    U64 d; asm("fma.rn.f32x2 %0,%1,%2,%3;" : "=l"(d) : "l"(a), "l"(b), "l"(c)); return d;
}
__device__ __forceinline__ void unp2(U64 v, float& a, float& b) {
    asm("mov.b64 {%0,%1},%2;" : "=f"(a), "=f"(b) : "l"(v));
}
__device__ __forceinline__ U64 wred(U64 v) {
#pragma unroll
    for (int o = 16; o; o >>= 1) {
        U64 t = __shfl_down_sync(0xffffffffu, v, o);
        if (t > v) v = t;
    }
    return v;
}
__device__ __forceinline__ float decode_w(const void* p) {
    int iv = *(const int*)p;
    if (iv > -100000000 && iv < 100000000) return (float)iv;
    return __int_as_float(iv);
}
__device__ __forceinline__ uint32_t pkbf(__nv_bfloat16 a, __nv_bfloat16 b) {
    unsigned short ua = __bfloat16_as_ushort(a), ub = __bfloat16_as_ushort(b);
    return (uint32_t)ua | ((uint32_t)ub << 16);
}
__device__ __forceinline__ uint32_t smem_u32(const void* p) {
    uint32_t a;
    asm("{ .reg .u64 t; cvta.to.shared.u64 t, %1; cvt.u32.u64 %0, t; }" : "=r"(a) : "l"(p));
    return a;
}
// ---- mma.sync helpers (compute_80+, pass the compute_103 PTX stage) ----
__device__ __forceinline__ void ldsm4(uint32_t& r0, uint32_t& r1, uint32_t& r2,
                                      uint32_t& r3, uint32_t addr) {
    asm volatile("ldmatrix.sync.aligned.m8n8.x4.shared.b16 {%0,%1,%2,%3}, [%4];"
                 : "=r"(r0), "=r"(r1), "=r"(r2), "=r"(r3) : "r"(addr));
}
__device__ __forceinline__ void mma16816(float* d, const uint32_t* a, uint32_t b0,
                                         uint32_t b1) {
    asm volatile("mma.sync.aligned.m16n8k16.row.col.f32.bf16.bf16.f32 "
                 "{%0,%1,%2,%3}, {%4,%5,%6,%7}, {%8,%9}, {%0,%1,%2,%3};"
                 : "+f"(d[0]), "+f"(d[1]), "+f"(d[2]), "+f"(d[3])
                 : "r"(a[0]), "r"(a[1]), "r"(a[2]), "r"(a[3]), "r"(b0), "r"(b1));
}

// ---------------- K0: init packed-argmax scratch ----------------
__global__ void k0_init() {
    int i = blockIdx.x * 256 + threadIdx.x;
    if (i < NP) { g_amax[i] = 0ull; g_avq[i] = 0ull; }
}

// ---------------- K1: two 1x1 convs ----------------
__global__ void k1_quant(const float* __restrict__ z_t, const float* __restrict__ qw,
                         const float* __restrict__ qb, const float* __restrict__ zlpre,
                         const float* __restrict__ lw, const float* __restrict__ lb,
                         float* __restrict__ out) {
    int id = blockIdx.x * 256 + threadIdx.x;     // 131072
    int which = id >> 16;
    int sub = id & 65535;
    int b = sub >> 14, e = (sub >> 10) & 15, hw = sub & 1023;
    if (which == 0) {
        const float* src = z_t + b * 65536 + hw;
        const float* w = qw + e * 64;
        float acc = qb[e];
#pragma unroll 16
        for (int c = 0; c < 64; c++) acc = fmaf(w[c], src[c * 1024], acc);
        g_z[(b * 1024 + hw) * 16 + e] = acc;
    } else {
        const float* src = zlpre + b * 65536 + hw;
        const float* w = lw + e * 64;
        float acc = lb[e];
#pragma unroll 16
        for (int c = 0; c < 64; c++) acc = fmaf(w[c], src[c * 1024], acc);
        out[OFF_ZL + b * 16384 + e * 1024 + hw] = acc;
    }
}

// ---------------- Kcn: |codebook|^2 ----------------
__global__ void kcn(const float* __restrict__ cb) {
    int n = blockIdx.x * 256 + threadIdx.x;
    float s = 0.f;
#pragma unroll
    for (int q = 0; q < 4; q++) {
        float4 v = *(const float4*)&cb[(size_t)n * 16 + q * 4];
        s = fmaf(v.x, v.x, s); s = fmaf(v.y, v.y, s);
        s = fmaf(v.z, v.z, s); s = fmaf(v.w, v.w, s);
    }
    g_cn[n] = s;
}

// ---------------- K2: VQ argmin (argmax of z.c - 0.5|c|^2), f32x2 ----------------
__global__ void __launch_bounds__(256) k2_vq(const float* __restrict__ cb) {
    __shared__ float cs[128 * 17];
    int tid = threadIdx.x;
    int wr = tid >> 5, lane = tid & 31;
    int pb = blockIdx.x * 32 + wr * 4;
    int cbase = blockIdx.y * 4096;

    U64 z2[2][16];
#pragma unroll
    for (int i2 = 0; i2 < 2; i2++) {
        float za[16], zb[16];
#pragma unroll
        for (int q = 0; q < 4; q++) {
            float4 v0 = *(const float4*)&g_z[(pb + 2 * i2) * 16 + q * 4];
            float4 v1 = *(const float4*)&g_z[(pb + 2 * i2 + 1) * 16 + q * 4];
            za[q * 4 + 0] = v0.x; za[q * 4 + 1] = v0.y; za[q * 4 + 2] = v0.z; za[q * 4 + 3] = v0.w;
            zb[q * 4 + 0] = v1.x; zb[q * 4 + 1] = v1.y; zb[q * 4 + 2] = v1.z; zb[q * 4 + 3] = v1.w;
        }
#pragma unroll
        for (int k = 0; k < 16; k++) z2[i2][k] = pk2(za[k], zb[k]);
    }

    float best[4]; int bn[4];
#pragma unroll
    for (int i = 0; i < 4; i++) { best[i] = -3.4e38f; bn[i] = 0; }

    for (int ch = 0; ch < 32; ch++) {
        int c0 = cbase + ch * 128;
        __syncthreads();
#pragma unroll
        for (int r = 0; r < 2; r++) {
            int f = tid + 256 * r;
            int code = f >> 2, kq = f & 3;
            float4 v = *(const float4*)&cb[(size_t)(c0 + code) * 16 + kq * 4];
            cs[code * 17 + kq * 4 + 0] = v.x; cs[code * 17 + kq * 4 + 1] = v.y;
            cs[code * 17 + kq * 4 + 2] = v.z; cs[code * 17 + kq * 4 + 3] = v.w;
        }
        __syncthreads();

        U64 acc2[2][4];
#pragma unroll
        for (int i2 = 0; i2 < 2; i2++)
#pragma unroll
            for (int j = 0; j < 4; j++) acc2[i2][j] = 0ull;

#pragma unroll
        for (int k = 0; k < 16; k++) {
            U64 cvp[4];
#pragma unroll
            for (int j = 0; j < 4; j++) {
                float cv = cs[(lane + 32 * j) * 17 + k];
                cvp[j] = pk2(cv, cv);
            }
#pragma unroll
            for (int i2 = 0; i2 < 2; i2++)
#pragma unroll
                for (int j = 0; j < 4; j++) acc2[i2][j] = fma2(z2[i2][k], cvp[j], acc2[i2][j]);
        }

#pragma unroll
        for (int j = 0; j < 4; j++) {
            int n = c0 + lane + 32 * j;
            float hn = 0.5f * __ldg(&g_cn[n]);
#pragma unroll
            for (int i2 = 0; i2 < 2; i2++) {
                float s0, s1; unp2(acc2[i2][j], s0, s1);
                s0 -= hn; s1 -= hn;
                int i = 2 * i2;
                if (s0 > best[i]) { best[i] = s0; bn[i] = n; }
                if (s1 > best[i + 1]) { best[i + 1] = s1; bn[i + 1] = n; }
            }
        }
    }
#pragma unroll
    for (int i = 0; i < 4; i++) {
        U64 pk = ((U64)ordf(best[i]) << 32) | (unsigned)(NNE - 1 - bn[i]);
        pk = wred(pk);
        if (lane == 0) atomicMax(&g_avq[pb + i], pk);
    }
}

// ---------------- K2b: finalize VQ ----------------
__global__ void k2b_fin(const float* __restrict__ cb, float* __restrict__ out) {
    int id = blockIdx.x * 256 + threadIdx.x;
    int p = id >> 4, e = id & 15;
    U64 pk = g_avq[p];
    int idx = NNE - 1 - (int)(unsigned)(pk & 0xffffffffu);
    int b = p >> 10, hw = p & 1023;
    out[OFF_ZHQ + b * 16384 + e * 1024 + hw] = __ldg(&cb[(size_t)idx * 16 + e]);
    if (e == 0) out[OFF_TI + p] = (float)idx;
}

// ---------------- K3: pcn 7x7 conv + relu -> g_h (k-major) ----------------
__global__ void __launch_bounds__(128) k3_pcn(const float* __restrict__ zl,
                                              const float* __restrict__ w1,
                                              const float* __restrict__ b1) {
    __shared__ float si[16 * 7 * 38];
    __shared__ float sw[8 * 784];
    int tid = threadIdx.x;
    int ocg = blockIdx.x, y = blockIdx.y, b = blockIdx.z;
    for (int idx = tid; idx < 16 * 266; idx += 128) {
        int ic = idx / 266; int rem = idx - ic * 266;
        int ky = rem / 38; int xx = rem - ky * 38;
        int yy = y - 3 + ky, xr = xx - 3;
        float v = 0.f;
        if ((unsigned)yy < 32u && (unsigned)xr < 32u)
            v = zl[b * 16384 + ic * 1024 + yy * 32 + xr];
        si[idx] = v;
    }
    for (int idx = tid; idx < 8 * 784; idx += 128) {
        int ol = idx / 784; int rem = idx - ol * 784;
        sw[idx] = w1[(ocg * 8 + ol) * 784 + rem];
    }
    __syncthreads();
    int ol = tid >> 4, xg = tid & 15, x0 = xg * 2;
    int oc = ocg * 8 + ol;
    float a0 = b1[oc], a1 = a0;
    for (int ic = 0; ic < 16; ic++) {
#pragma unroll
        for (int ky = 0; ky < 7; ky++) {
            const float* sp = &si[ic * 266 + ky * 38 + x0];
            float r[8];
#pragma unroll
            for (int j = 0; j < 8; j++) r[j] = sp[j];
            const float* wp = &sw[ol * 784 + ic * 49 + ky * 7];
#pragma unroll
            for (int kx = 0; kx < 7; kx++) {
                float wv = wp[kx];
                a0 = fmaf(r[kx], wv, a0);
                a1 = fmaf(r[kx + 1], wv, a1);
            }
        }
    }
    a0 = fmaxf(a0, 0.f); a1 = fmaxf(a1, 0.f);
    int p = b * 1024 + y * 32 + x0;
    g_h[oc * 4096 + p] = a0;
    g_h[oc * 4096 + p + 1] = a1;
}

// ---------------- Kprep_b: B_ext [n][192 bf16] : seg0=hi seg1=hi seg2=lo ----------------
__global__ void kprep_b(const float* __restrict__ w2) {
    int id = blockIdx.x * 256 + threadIdx.x;   // 1572864
    int n = id / 96, j = id - n * 96;
    int kp = 2 * j, seg = kp >> 6, kk = kp & 63;
    float x0 = w2[(size_t)n * 64 + kk];
    float x1 = w2[(size_t)n * 64 + kk + 1];
    __nv_bfloat16 h0 = __float2bfloat16(x0), h1 = __float2bfloat16(x1);
    __nv_bfloat16 v0, v1;
    if (seg == 2) {
        v0 = __float2bfloat16(x0 - __bfloat162float(h0));
        v1 = __float2bfloat16(x1 - __bfloat162float(h1));
    } else { v0 = h0; v1 = h1; }
    g_bext[(size_t)n * 96 + j] = pkbf(v0, v1);
}

// ---------------- Kprep_a: A_ext [p][192 bf16] : seg0=hi seg1=lo seg2=hi ----------------
__global__ void kprep_a() {
    int id = blockIdx.x * 256 + threadIdx.x;  // 393216
    int j = id >> 12, p = id & 4095;
    int kp = 2 * j, seg = kp >> 6, kk = kp & 63;
    float x0 = g_h[kk * 4096 + p];
    float x1 = g_h[(kk + 1) * 4096 + p];
    __nv_bfloat16 h0 = __float2bfloat16(x0), h1 = __float2bfloat16(x1);
    __nv_bfloat16 v0, v1;
    if (seg == 1) {
        v0 = __float2bfloat16(x0 - __bfloat162float(h0));
        v1 = __float2bfloat16(x1 - __bfloat162float(h1));
    } else { v0 = h0; v1 = h1; }
    g_aext[p * 96 + j] = pkbf(v0, v1);
}

// ---------------- K4M: logits GEMM via mma.sync bf16 (K=192 compensated) ----------------
// CTA 128p x 128n, 8 warps (4m x 2n), warp 32p x 64n. Row stride 108 u32 (432B):
// 8-row ldmatrix bank starts 12*{0..7} mod 32 -> spans tile all 32 banks once.
#define AST 108  // u32 per smem row
__global__ void __launch_bounds__(256) k4m(const float* __restrict__ b2,
                                           float* __restrict__ out) {
    extern __shared__ __align__(16) uint32_t dyn[];
    uint32_t* As = dyn;                 // 128*108 u32
    uint32_t* Bs = dyn + 128 * AST;     // 128*108 u32
    __shared__ float sbias[128];
    int tid = threadIdx.x;
    int n0 = blockIdx.x * 128, p0 = blockIdx.y * 128;
    if (tid < 128) sbias[tid] = b2[n0 + tid];
    for (int i = tid; i < 3072; i += 256) {
        int row = i / 24, j = i - row * 24;
        *(uint4*)&As[row * AST + j * 4] = *(const uint4*)&g_aext[(p0 + row) * 96 + j * 4];
        *(uint4*)&Bs[row * AST + j * 4] =
            *(const uint4*)&g_bext[(size_t)(n0 + row) * 96 + j * 4];
    }
    __syncthreads();
    int w = tid >> 5, lane = tid & 31;
    int wm = w & 3, wn = w >> 2;
    uint32_t abase = smem_u32(As) + (wm * 32 + (lane & 15)) * 432 + (lane >> 4) * 16;
    uint32_t bbase = smem_u32(Bs) + (wn * 64 + (lane & 15)) * 432 + (lane >> 4) * 16;

    float acc[2][8][4];
#pragma unroll
    for (int mi = 0; mi < 2; mi++)
#pragma unroll
        for (int nf = 0; nf < 8; nf++)
#pragma unroll
            for (int q = 0; q < 4; q++) acc[mi][nf][q] = 0.f;

#pragma unroll
    for (int ks = 0; ks < 12; ks++) {
        uint32_t a[2][4];
        ldsm4(a[0][0], a[0][1], a[0][2], a[0][3], abase + ks * 32);
        ldsm4(a[1][0], a[1][1], a[1][2], a[1][3], abase + 16 * 432 + ks * 32);
        uint32_t bf[8][2];
#pragma unroll
        for (int t = 0; t < 4; t++) {
            uint32_t r0, r1, r2, r3;
            ldsm4(r0, r1, r2, r3, bbase + t * 16 * 432 + ks * 32);
            bf[t * 2][0] = r0; bf[t * 2][1] = r2;
            bf[t * 2 + 1][0] = r1; bf[t * 2 + 1][1] = r3;
        }
#pragma unroll
        for (int mi = 0; mi < 2; mi++)
#pragma unroll
            for (int nf = 0; nf < 8; nf++)
                mma16816(acc[mi][nf], a[mi], bf[nf][0], bf[nf][1]);
    }

    int lq = lane >> 2, lr = lane & 3;
    float bias0[8], bias1[8];
#pragma unroll
    for (int nf = 0; nf < 8; nf++) {
        bias0[nf] = sbias[wn * 64 + nf * 8 + 2 * lr];
        bias1[nf] = sbias[wn * 64 + nf * 8 + 2 * lr + 1];
    }
#pragma unroll
    for (int mi = 0; mi < 2; mi++) {
#pragma unroll
        for (int hf = 0; hf < 2; hf++) {
            int r = p0 + wm * 32 + mi * 16 + hf * 8 + lq;
            float best = -3.4e38f; int bestn = 0;
            float* orow = &out[(size_t)r * NNE + n0 + wn * 64 + 2 * lr];
#pragma unroll
            for (int nf = 0; nf < 8; nf++) {
                float v0 = acc[mi][nf][hf * 2] + bias0[nf];
                float v1 = acc[mi][nf][hf * 2 + 1] + bias1[nf];
                *(float2*)&orow[nf * 8] = make_float2(v0, v1);
                int c = n0 + wn * 64 + nf * 8 + 2 * lr;
                if (v0 > best) { best = v0; bestn = c; }
                if (v1 > best) { best = v1; bestn = c + 1; }
            }
            U64 pk = ((U64)ordf(best) << 32) | (unsigned)(NNE - 1 - bestn);
#pragma unroll
            for (int o = 1; o <= 2; o <<= 1) {
                U64 t = __shfl_xor_sync(0xffffffffu, pk, o);
                if (t > pk) pk = t;
            }
            if (lr == 0) atomicMax(&g_amax[r], pk);
        }
    }
}

// ---------------- K5: z_lq = post_quant_conv(codebook[top_index]) ----------------
__global__ void k5_zlq(const float* __restrict__ cb, const float* __restrict__ pqw,
                       const float* __restrict__ pqb) {
    int id = blockIdx.x * 256 + threadIdx.x;  // 262144
    int p = id >> 6, zc = id & 63;
    U64 pk = g_amax[p];
    int idx = NNE - 1 - (int)(unsigned)(pk & 0xffffffffu);
    const float* c = &cb[(size_t)idx * 16];
    float a = pqb[zc];
#pragma unroll
    for (int k = 0; k < 16; k++) a = fmaf(pqw[zc * 16 + k], __ldg(&c[k]), a);
    g_zlq[((p >> 10) * 64 + zc) * 1024 + (p & 1023)] = a;
}

// ---------------- conv3x3 (dec1 / fuse) ----------------
template <int W, int MODE>
__global__ void __launch_bounds__(256) conv3(const float* __restrict__ in,
                                             const float* __restrict__ wt,
                                             const float* __restrict__ bs,
                                             const void* __restrict__ wraw) {
    constexpr int WP = W + 2;
    constexpr int OCT = W / 8;
    __shared__ float sin_[16][6][WP];
    __shared__ float sw[32 * 144];
    int tid = threadIdx.x;
    int strip = blockIdx.x, ocg = blockIdx.y, b = blockIdx.z;
    int x = tid % W, og = tid / W;
    const float* src = (MODE == 0) ? (const float*)g_zlq : in;
    float acc[OCT][4];
#pragma unroll
    for (int t = 0; t < OCT; t++)
#pragma unroll
        for (int y = 0; y < 4; y++) acc[t][y] = 0.f;
    int y0 = strip * 4;

    for (int icc = 0; icc < 4; icc++) {
        __syncthreads();
        for (int idx = tid; idx < 16 * 6 * WP; idx += 256) {
            int ic = idx / (6 * WP); int rem = idx - ic * 6 * WP;
            int r = rem / WP; int c = rem - r * WP;
            int gy = y0 - 1 + r, gx = c - 1;
            float v = 0.f;
            if ((unsigned)gy < (unsigned)W && (unsigned)gx < (unsigned)W)
                v = src[((b * 64 + icc * 16 + ic) * W + gy) * W + gx];
            sin_[ic][r][c] = v;
        }
        for (int idx = tid; idx < 32 * 144; idx += 256) {
            int ol = idx / 144; int rem = idx - ol * 144;
            sw[idx] = wt[(ocg * 32 + ol) * 576 + icc * 144 + rem];
        }
        __syncthreads();
        for (int ic = 0; ic < 16; ic++) {
            float rv[6][3];
#pragma unroll
            for (int r = 0; r < 6; r++)
#pragma unroll
                for (int cc = 0; cc < 3; cc++) rv[r][cc] = sin_[ic][r][x + cc];
#pragma unroll
            for (int t = 0; t < OCT; t++) {
                const float* wp = &sw[(og * OCT + t) * 144 + ic * 9];
#pragma unroll
                for (int ky = 0; ky < 3; ky++)
#pragma unroll
                    for (int kx = 0; kx < 3; kx++) {
                        float wv = wp[ky * 3 + kx];
#pragma unroll
                        for (int y = 0; y < 4; y++)
                            acc[t][y] = fmaf(rv[y + ky][kx], wv, acc[t][y]);
                    }
            }
        }
    }
    float ws = 1.f;
    if (MODE == 1) ws = decode_w(wraw);
#pragma unroll
    for (int t = 0; t < OCT; t++) {
        int oc = ocg * 32 + og * OCT + t;
        float bv = bs[oc];
#pragma unroll
        for (int y = 0; y < 4; y++) {
            int oy = y0 + y;
            float v = acc[t][y] + bv;
            if (MODE == 0) {
                v = fmaxf(v, 0.f);
                g_t1[((b * 64 + oc) << 10) + oy * 32 + x] = v;
            } else {
                float base = g_t1[((b * 64 + oc) << 10) + ((oy >> 1) << 5) + (x >> 1)];
                v = fmaxf(base + ws * v, 0.f);
                g_t2[((b * 64 + oc) << 12) + (oy << 6) + x] = v;
            }
        }
    }
}

// ---------------- K8: dec2 = conv3x3(up2(g_t2)) -> out ----------------
__global__ void __launch_bounds__(256) k8_dec2(const float* __restrict__ w2,
                                               const float* __restrict__ b2,
                                               float* __restrict__ out) {
    __shared__ float wq[16][64];
    int tid = threadIdx.x;
    for (int idx = tid; idx < 1024; idx += 256) {
        int c = idx & 63; int m = idx >> 6;
        int py = m >> 3, px = (m >> 2) & 1, j = (m >> 1) & 1, i = m & 1;
        int ky0 = (py == 0) ? (j == 0 ? 0 : 1) : (j == 0 ? 0 : 2);
        int kyn = (py == 0) ? (j == 0 ? 1 : 2) : (j == 0 ? 2 : 1);
        int kx0 = (px == 0) ? (i == 0 ? 0 : 1) : (i == 0 ? 0 : 2);
        int kxn = (px == 0) ? (i == 0 ? 1 : 2) : (i == 0 ? 2 : 1);
        float s = 0.f;
        for (int ky = ky0; ky < ky0 + kyn; ky++)
            for (int kx = kx0; kx < kx0 + kxn; kx++)
                s += w2[c * 9 + ky * 3 + kx];
        wq[m][c] = s;
    }
    __syncthreads();
    int q = blockIdx.x * 256 + tid;
    int b = q >> 12; int r = q & 4095; int qy = r >> 6; int qx = r & 63;
    float bb = b2[0];
    float acc[2][2] = {{bb, bb}, {bb, bb}};
    for (int c = 0; c < 64; c++) {
        const float* base = &g_t2[((b * 64 + c) << 12)];
        float v[3][3];
#pragma unroll
        for (int dj = 0; dj < 3; dj++) {
            int ry = qy - 1 + dj;
#pragma unroll
            for (int di = 0; di < 3; di++) {
                int rx = qx - 1 + di;
                v[dj][di] = ((unsigned)ry < 64u && (unsigned)rx < 64u)
                                ? __ldg(&base[(ry << 6) + rx]) : 0.f;
            }
        }
#pragma unroll
        for (int py = 0; py < 2; py++)
#pragma unroll
            for (int px = 0; px < 2; px++)
#pragma unroll
                for (int j = 0; j < 2; j++)
#pragma unroll
                    for (int i = 0; i < 2; i++)
                        acc[py][px] = fmaf(wq[(py * 2 + px) * 4 + j * 2 + i][c],
                                           v[py + j][px + i], acc[py][px]);
    }
#pragma unroll
    for (int py = 0; py < 2; py++)
#pragma unroll
        for (int px = 0; px < 2; px++)
            out[OFF_DEC + (b << 14) + ((2 * qy + py) << 7) + 2 * qx + px] = acc[py][px];
}

// ---------------- launch ----------------
extern "C" void kernel_launch(void* const* d_in, const int* in_sizes, int n_in,
                              void* d_out, int out_size) {
    const float* z_t      = (const float*)d_in[0];
    const float* z_l_pre  = (const float*)d_in[1];
    const float* fuse_feat= (const float*)d_in[2];
    const void*  wraw     = d_in[3];
    const float* quant_w  = (const float*)d_in[4];
    const float* quant_b  = (const float*)d_in[5];
    const float* codebook = (const float*)d_in[6];
    const float* lrq_w    = (const float*)d_in[7];
    const float* lrq_b    = (const float*)d_in[8];
    const float* pcn_w1   = (const float*)d_in[9];
    const float* pcn_b1   = (const float*)d_in[10];
    const float* pcn_w2   = (const float*)d_in[11];
    const float* pcn_b2   = (const float*)d_in[12];
    const float* pq_w     = (const float*)d_in[13];
    const float* pq_b     = (const float*)d_in[14];
    const float* dec_w1   = (const float*)d_in[15];
    const float* dec_b1   = (const float*)d_in[16];
    const float* fuse_w   = (const float*)d_in[17];
    const float* fuse_b   = (const float*)d_in[18];
    const float* dec_w2   = (const float*)d_in[19];
    const float* dec_b2   = (const float*)d_in[20];
    float* out = (float*)d_out;

    cudaFuncSetAttribute(k4m, cudaFuncAttributeMaxDynamicSharedMemorySize, 110592);

    k0_init<<<16, 256>>>();
    kprep_b<<<6144, 256>>>(pcn_w2);
    k1_quant<<<512, 256>>>(z_t, quant_w, quant_b, z_l_pre, lrq_w, lrq_b, out);
    kcn<<<64, 256>>>(codebook);
    k2_vq<<<dim3(128, 4), 256>>>(codebook);
    k2b_fin<<<256, 256>>>(codebook, out);
    k3_pcn<<<dim3(8, 32, 4), 128>>>(out + OFF_ZL, pcn_w1, pcn_b1);
    kprep_a<<<1536, 256>>>();
    k4m<<<dim3(128, 32), 256, 110592>>>(pcn_b2, out);
    k5_zlq<<<1024, 256>>>(codebook, pq_w, pq_b);
    conv3<32, 0><<<dim3(8, 2, 4), 256>>>(nullptr, dec_w1, dec_b1, nullptr);
    conv3<64, 1><<<dim3(16, 2, 4), 256>>>(fuse_feat, fuse_w, fuse_b, wraw);
    k8_dec2<<<64, 256>>>(dec_w2, dec_b2, out);
}